// round 1
// baseline (speedup 1.0000x reference)
#include <cuda_runtime.h>
#include <math.h>

#define D_MODEL 2048
#define NEXP    128
#define BM      64
#define BK      32
#define NTHREADS 256
#define TOPK    8

struct SmemT {
    union {
        struct {
            float As[BK][BM];     // x tile, transposed: As[k][m]
            float Bs[BK][NEXP];   // w tile, transposed: Bs[k][e]
        } g;
        float Ls[BM][NEXP];       // logits tile for epilogue
    };
};

__global__ __launch_bounds__(NTHREADS, 2)
void moe_router_kernel(const float* __restrict__ X,
                       const float* __restrict__ W,
                       const float* __restrict__ BIAS,
                       float* __restrict__ OUTW,
                       float* __restrict__ OUTI,
                       int writeIdx, int Ntok)
{
    __shared__ SmemT sm;
    const int tid = threadIdx.x;
    const int bm0 = blockIdx.x * BM;

    // register micro-tile mapping: 4 tokens x 8 experts per thread
    const int tm = (tid & 15) * 4;   // token row base within tile
    const int te = (tid >> 4) * 8;   // expert base

    // ---- global load index precompute ----
    int ra[2], ca[2];                 // x tile: 64 rows x 32 cols, 2 float4/thread
#pragma unroll
    for (int p = 0; p < 2; ++p) {
        int q = tid + NTHREADS * p;
        ra[p] = q >> 3;
        ca[p] = (q & 7) * 4;
    }
    int re[4], ce[4];                 // w tile: 128 rows x 32 cols, 4 float4/thread
#pragma unroll
    for (int p = 0; p < 4; ++p) {
        int q = tid + NTHREADS * p;
        re[p] = q >> 3;
        ce[p] = (q & 7) * 4;
    }

    float4 axr[2], bwr[4];
    // prologue: load tile 0
    {
        const int k0 = 0;
#pragma unroll
        for (int p = 0; p < 2; ++p) {
            int row = bm0 + ra[p];
            axr[p] = (row < Ntok)
                ? *reinterpret_cast<const float4*>(X + (size_t)row * D_MODEL + k0 + ca[p])
                : make_float4(0.f, 0.f, 0.f, 0.f);
        }
#pragma unroll
        for (int p = 0; p < 4; ++p)
            bwr[p] = *reinterpret_cast<const float4*>(W + (size_t)re[p] * D_MODEL + k0 + ce[p]);
    }

    float acc[4][8];
#pragma unroll
    for (int i = 0; i < 4; ++i)
#pragma unroll
        for (int j = 0; j < 8; ++j)
            acc[i][j] = 0.f;

    const int NKT = D_MODEL / BK;   // 64
    for (int kt = 0; kt < NKT; ++kt) {
        // stage current tile into smem (transposed)
#pragma unroll
        for (int p = 0; p < 2; ++p) {
            sm.g.As[ca[p] + 0][ra[p]] = axr[p].x;
            sm.g.As[ca[p] + 1][ra[p]] = axr[p].y;
            sm.g.As[ca[p] + 2][ra[p]] = axr[p].z;
            sm.g.As[ca[p] + 3][ra[p]] = axr[p].w;
        }
#pragma unroll
        for (int p = 0; p < 4; ++p) {
            sm.g.Bs[ce[p] + 0][re[p]] = bwr[p].x;
            sm.g.Bs[ce[p] + 1][re[p]] = bwr[p].y;
            sm.g.Bs[ce[p] + 2][re[p]] = bwr[p].z;
            sm.g.Bs[ce[p] + 3][re[p]] = bwr[p].w;
        }
        __syncthreads();

        // prefetch next tile into registers (overlaps with compute)
        if (kt + 1 < NKT) {
            const int k0 = (kt + 1) * BK;
#pragma unroll
            for (int p = 0; p < 2; ++p) {
                int row = bm0 + ra[p];
                axr[p] = (row < Ntok)
                    ? *reinterpret_cast<const float4*>(X + (size_t)row * D_MODEL + k0 + ca[p])
                    : make_float4(0.f, 0.f, 0.f, 0.f);
            }
#pragma unroll
            for (int p = 0; p < 4; ++p)
                bwr[p] = *reinterpret_cast<const float4*>(W + (size_t)re[p] * D_MODEL + k0 + ce[p]);
        }

        // compute 32 k-steps
#pragma unroll 8
        for (int k = 0; k < BK; ++k) {
            float4 a4  = *reinterpret_cast<const float4*>(&sm.g.As[k][tm]);
            float4 b04 = *reinterpret_cast<const float4*>(&sm.g.Bs[k][te]);
            float4 b14 = *reinterpret_cast<const float4*>(&sm.g.Bs[k][te + 4]);
            float av[4] = {a4.x, a4.y, a4.z, a4.w};
            float bv[8] = {b04.x, b04.y, b04.z, b04.w, b14.x, b14.y, b14.z, b14.w};
#pragma unroll
            for (int mi = 0; mi < 4; ++mi)
#pragma unroll
                for (int ni = 0; ni < 8; ++ni)
                    acc[mi][ni] = fmaf(av[mi], bv[ni], acc[mi][ni]);
        }
        __syncthreads();   // protect smem before next stage's stores
    }

    // ---- write logits tile to smem ----
#pragma unroll
    for (int mi = 0; mi < 4; ++mi) {
        *reinterpret_cast<float4*>(&sm.Ls[tm + mi][te]) =
            make_float4(acc[mi][0], acc[mi][1], acc[mi][2], acc[mi][3]);
        *reinterpret_cast<float4*>(&sm.Ls[tm + mi][te + 4]) =
            make_float4(acc[mi][4], acc[mi][5], acc[mi][6], acc[mi][7]);
    }
    __syncthreads();

    // ---- router epilogue: 1 warp per token ----
    const int lane = tid & 31;
    const int wrp  = tid >> 5;

    for (int t = wrp; t < BM; t += (NTHREADS / 32)) {
        int gt = bm0 + t;
        if (gt >= Ntok) continue;

        float v0 = sm.Ls[t][lane];
        float v1 = sm.Ls[t][lane + 32];
        float v2 = sm.Ls[t][lane + 64];
        float v3 = sm.Ls[t][lane + 96];

        // softmax over 128
        float mx = fmaxf(fmaxf(v0, v1), fmaxf(v2, v3));
#pragma unroll
        for (int off = 16; off > 0; off >>= 1)
            mx = fmaxf(mx, __shfl_xor_sync(0xffffffffu, mx, off));

        float e0 = expf(v0 - mx);
        float e1 = expf(v1 - mx);
        float e2 = expf(v2 - mx);
        float e3 = expf(v3 - mx);
        float sum = e0 + e1 + e2 + e3;
#pragma unroll
        for (int off = 16; off > 0; off >>= 1)
            sum += __shfl_xor_sync(0xffffffffu, sum, off);

        float s0 = e0 / sum, s1 = e1 / sum, s2 = e2 / sum, s3 = e3 / sum;

        // bias-adjusted scores for selection only
        float bb0 = s0 + __ldg(BIAS + lane);
        float bb1 = s1 + __ldg(BIAS + lane + 32);
        float bb2 = s2 + __ldg(BIAS + lane + 64);
        float bb3 = s3 + __ldg(BIAS + lane + 96);

        float topw[TOPK];
        int   topi[TOPK];

#pragma unroll
        for (int i = 0; i < TOPK; ++i) {
            // local best among this lane's 4 experts (ascending idx, strict > => lower idx wins ties)
            float bv = bb0; int bi = lane;
            if (bb1 > bv) { bv = bb1; bi = lane + 32; }
            if (bb2 > bv) { bv = bb2; bi = lane + 64; }
            if (bb3 > bv) { bv = bb3; bi = lane + 96; }
            // warp reduce with tie-break on smaller index (matches jax.lax.top_k)
#pragma unroll
            for (int off = 16; off > 0; off >>= 1) {
                float ov = __shfl_xor_sync(0xffffffffu, bv, off);
                int   oi = __shfl_xor_sync(0xffffffffu, bi, off);
                if (ov > bv || (ov == bv && oi < bi)) { bv = ov; bi = oi; }
            }
            topi[i] = bi;
            int src = bi & 31, slot = bi >> 5;
            float sv = (slot == 0) ? s0 : (slot == 1) ? s1 : (slot == 2) ? s2 : s3;
            sv = __shfl_sync(0xffffffffu, sv, src);
            topw[i] = sv;
            if (lane == src) {
                if      (slot == 0) bb0 = -INFINITY;
                else if (slot == 1) bb1 = -INFINITY;
                else if (slot == 2) bb2 = -INFINITY;
                else                bb3 = -INFINITY;
            }
        }

        float n2 = 0.f;
#pragma unroll
        for (int i = 0; i < TOPK; ++i) n2 += topw[i] * topw[i];
        float nrm = sqrtf(n2);

        if (lane == 0) {
            size_t base = (size_t)gt * TOPK;
            float4 w0 = make_float4(topw[0] / nrm, topw[1] / nrm, topw[2] / nrm, topw[3] / nrm);
            float4 w1 = make_float4(topw[4] / nrm, topw[5] / nrm, topw[6] / nrm, topw[7] / nrm);
            *reinterpret_cast<float4*>(&OUTW[base])     = w0;
            *reinterpret_cast<float4*>(&OUTW[base + 4]) = w1;
            if (writeIdx) {
                float4 i0 = make_float4((float)topi[0], (float)topi[1], (float)topi[2], (float)topi[3]);
                float4 i1 = make_float4((float)topi[4], (float)topi[5], (float)topi[6], (float)topi[7]);
                *reinterpret_cast<float4*>(&OUTI[base])     = i0;
                *reinterpret_cast<float4*>(&OUTI[base + 4]) = i1;
            }
        }
    }
}

extern "C" void kernel_launch(void* const* d_in, const int* in_sizes, int n_in,
                              void* d_out, int out_size)
{
    const float* x    = (const float*)d_in[0];   // (B*S, D) fp32
    const float* w    = (const float*)d_in[1];   // (E, D) fp32
    const float* bias = (const float*)d_in[2];   // (E,) fp32

    const int Ntok = in_sizes[0] / D_MODEL;      // 16384

    float* outw = (float*)d_out;
    // Output layout guess: [expert_weights (N*8)] then [expert_indices (N*8) as float],
    // falling back to weights-only if out_size is smaller.
    int writeIdx = (out_size >= 2 * Ntok * TOPK) ? 1 : 0;
    float* outi = outw + (size_t)Ntok * TOPK;

    int grid = (Ntok + BM - 1) / BM;
    moe_router_kernel<<<grid, NTHREADS>>>(x, w, bias, outw, outi, writeIdx, Ntok);
}